// round 1
// baseline (speedup 1.0000x reference)
#include <cuda_runtime.h>
#include <cuda_bf16.h>

// Problem constants (fixed by the reference setup)
#define T_DIM   2048
#define NUM_SEG 64
#define SEG     32          // T / NUM_SEG
#define F_DIM   32
#define H_DIM   128
#define FEAT_DIM 4

// Block: 256 threads = 8 warps = 8 output rows, all within one segment.
// 4 blocks per segment -> 256 blocks total.
#define ROWS_PER_BLOCK 8
#define THREADS 256

__global__ __launch_bounds__(THREADS)
void horizon_attn_kernel(const float* __restrict__ f,
                         const float* __restrict__ h,
                         const float* __restrict__ features,
                         const float* __restrict__ hor,
                         const float* __restrict__ W_w,
                         const float* __restrict__ W_b,
                         float* __restrict__ S)
{
    __shared__ float h_seg[SEG][H_DIM];        // 16 KB
    __shared__ float Wh_seg[SEG][F_DIM + 1];   // +1 pad: avoid 32-way bank conflict

    const int tid    = threadIdx.x;
    const int blk    = blockIdx.x;
    const int seg    = blk >> 2;               // 4 blocks per segment
    const int rowgrp = blk & 3;
    const int seg0   = seg * SEG;

    // ---- Stage h_seg (32 x 128 floats) via float4 ----
    {
        const float4* h4  = reinterpret_cast<const float4*>(h + (size_t)seg0 * H_DIM);
        float4*       hs4 = reinterpret_cast<float4*>(&h_seg[0][0]);
        #pragma unroll
        for (int idx = tid; idx < SEG * H_DIM / 4; idx += THREADS)
            hs4[idx] = h4[idx];
    }
    __syncthreads();

    // ---- Wh_seg[j][ff] = W_b[ff] + dot(h_seg[j], W_w[ff]) ----
    // 1024 outputs, 256 threads -> 4 each. W_w rows read via float4 (L1/L2 cached).
    for (int o = tid; o < SEG * F_DIM; o += THREADS) {
        const int jj = o >> 5;
        const int ff = o & 31;
        const float4* wr = reinterpret_cast<const float4*>(W_w + (size_t)ff * H_DIM);
        const float4* hr = reinterpret_cast<const float4*>(&h_seg[jj][0]);
        float acc = W_b[ff];
        #pragma unroll
        for (int k = 0; k < H_DIM / 4; k++) {
            float4 w = wr[k];
            float4 hv = hr[k];
            acc += w.x * hv.x + w.y * hv.y + w.z * hv.z + w.w * hv.w;
        }
        Wh_seg[jj][ff] = acc;
    }
    __syncthreads();

    // ---- Per-warp row processing ----
    const int warp = tid >> 5;
    const int lane = tid & 31;
    const int i = seg0 + rowgrp * ROWS_PER_BLOCK + warp;   // global output row
    const int j = lane;                                    // column within segment
    const int gj = seg0 + j;                               // global column

    // logit_j = dot(f[i, gj, :], Wh_seg[j, :])  (32-dot, float4-vectorized)
    const size_t fbase = ((size_t)i * T_DIM + gj) * F_DIM;
    const float4* fp = reinterpret_cast<const float4*>(f + fbase);
    float logit = 0.f;
    #pragma unroll
    for (int k4 = 0; k4 < F_DIM / 4; k4++) {
        float4 v = fp[k4];
        logit += v.x * Wh_seg[j][k4 * 4 + 0]
               + v.y * Wh_seg[j][k4 * 4 + 1]
               + v.z * Wh_seg[j][k4 * 4 + 2]
               + v.w * Wh_seg[j][k4 * 4 + 3];
    }

    // bad mask: bearing < 0 || distance > 10 || self
    const size_t mbase = (size_t)i * T_DIM + gj;
    const bool bad = (hor[mbase] < 0.f)
                  || (features[mbase * FEAT_DIM] > 10.f)
                  || (i == gj);
    float val = bad ? -1000.f : logit;

    // warp softmax over the 32 in-segment entries (all others are -inf -> 0)
    float m = val;
    #pragma unroll
    for (int off = 16; off; off >>= 1)
        m = fmaxf(m, __shfl_xor_sync(0xFFFFFFFFu, m, off));
    float e = expf(val - m);
    float ssum = e;
    #pragma unroll
    for (int off = 16; off; off >>= 1)
        ssum += __shfl_xor_sync(0xFFFFFFFFu, ssum, off);
    const float attn = e / ssum;   // lane j holds attn[i, seg0+j]

    // S[i, :] = sum_j attn_j * h_seg[j, :]; lane owns cols {lane, lane+32, lane+64, lane+96}
    float acc0 = 0.f, acc1 = 0.f, acc2 = 0.f, acc3 = 0.f;
    #pragma unroll
    for (int jj = 0; jj < SEG; jj++) {
        const float a = __shfl_sync(0xFFFFFFFFu, attn, jj);
        acc0 += a * h_seg[jj][lane];
        acc1 += a * h_seg[jj][lane + 32];
        acc2 += a * h_seg[jj][lane + 64];
        acc3 += a * h_seg[jj][lane + 96];
    }

    // seg_size == 32 > 1 always, so no zeroing branch needed.
    float* out = S + (size_t)i * H_DIM;
    out[lane]      = acc0;
    out[lane + 32] = acc1;
    out[lane + 64] = acc2;
    out[lane + 96] = acc3;
}

extern "C" void kernel_launch(void* const* d_in, const int* in_sizes, int n_in,
                              void* d_out, int out_size)
{
    // metadata order: f, h, features, hor_bearings_MTX, W_w, W_b, sub_batches
    const float* f        = (const float*)d_in[0];
    const float* h        = (const float*)d_in[1];
    const float* features = (const float*)d_in[2];
    const float* hor      = (const float*)d_in[3];
    const float* W_w      = (const float*)d_in[4];
    const float* W_b      = (const float*)d_in[5];
    // d_in[6] = sub_batches (int64) — segments are fixed contiguous 32-blocks; unused.
    float* S = (float*)d_out;

    const int grid = (T_DIM / ROWS_PER_BLOCK);   // 256 blocks
    horizon_attn_kernel<<<grid, THREADS>>>(f, h, features, hor, W_w, W_b, S);
}

// round 2
// speedup vs baseline: 1.1046x; 1.1046x over previous
#include <cuda_runtime.h>
#include <cuda_bf16.h>

// Problem constants (fixed by the reference setup)
#define T_DIM    2048
#define NUM_SEG  64
#define SEG      32          // T / NUM_SEG
#define F_DIM    32
#define H_DIM    128
#define FEAT_DIM 4

#define ROWS_PER_BLOCK 8
#define THREADS 256

// Precomputed Wh = h @ W_w^T + W_b  (2048 x 32), written by wh_kernel.
__device__ float g_Wh[T_DIM * F_DIM];

// ---------------------------------------------------------------------------
// Kernel 1: Wh[row][col] = W_b[col] + dot(h[row], W_w[col])
// One thread per output element. Warp lanes share `row` (h loads broadcast),
// differ in `col` (W_w is 16 KB, L1-resident after first touch).
// ---------------------------------------------------------------------------
__global__ __launch_bounds__(THREADS, 2)
void wh_kernel(const float* __restrict__ h,
               const float* __restrict__ W_w,
               const float* __restrict__ W_b)
{
    const int t   = blockIdx.x * THREADS + threadIdx.x;   // 0 .. 65535
    const int row = t >> 5;
    const int col = t & 31;

    const float4* hr = reinterpret_cast<const float4*>(h   + (size_t)row * H_DIM);
    const float4* wr = reinterpret_cast<const float4*>(W_w + (size_t)col * H_DIM);

    float acc = W_b[col];
    #pragma unroll 8
    for (int k = 0; k < H_DIM / 4; k++) {
        float4 a = hr[k];
        float4 b = wr[k];
        acc += a.x * b.x + a.y * b.y + a.z * b.z + a.w * b.w;
    }
    g_Wh[t] = acc;   // coalesced: lanes write consecutive cols
}

// ---------------------------------------------------------------------------
// Kernel 2: block-diagonal masked softmax attention.
// 256 blocks x 256 threads; block = 8 rows of one segment (4 blocks/segment).
// All DRAM loads (f, hor, features) issued BEFORE staging/sync so their
// latency overlaps the smem staging + barrier.
// ---------------------------------------------------------------------------
__global__ __launch_bounds__(THREADS, 2)
void horizon_attn_kernel(const float* __restrict__ f,
                         const float* __restrict__ h,
                         const float* __restrict__ features,
                         const float* __restrict__ hor,
                         float* __restrict__ S)
{
    __shared__ float h_seg[SEG][H_DIM];          // 16 KB
    __shared__ float Wh_s[SEG][F_DIM + 1];       // pitch 33: conflict-free scalar reads

    const int tid    = threadIdx.x;
    const int blk    = blockIdx.x;
    const int seg    = blk >> 2;
    const int rowgrp = blk & 3;
    const int seg0   = seg * SEG;

    const int warp = tid >> 5;
    const int lane = tid & 31;
    const int i  = seg0 + rowgrp * ROWS_PER_BLOCK + warp;  // output row
    const int gj = seg0 + lane;                            // global column (this lane)

    // ---- Issue all DRAM loads early (independent of smem) ----
    float4 fv[F_DIM / 4];
    {
        const size_t fbase = ((size_t)i * T_DIM + gj) * F_DIM;
        const float4* fp = reinterpret_cast<const float4*>(f + fbase);
        #pragma unroll
        for (int k4 = 0; k4 < F_DIM / 4; k4++)
            fv[k4] = fp[k4];
    }
    const size_t mbase = (size_t)i * T_DIM + gj;
    const float bearing = hor[mbase];
    const float dist    = features[mbase * FEAT_DIM];

    // ---- Stage h_seg (32x128 f32) via float4 ----
    {
        const float4* h4  = reinterpret_cast<const float4*>(h + (size_t)seg0 * H_DIM);
        float4*       hs4 = reinterpret_cast<float4*>(&h_seg[0][0]);
        #pragma unroll
        for (int idx = tid; idx < SEG * H_DIM / 4; idx += THREADS)
            hs4[idx] = h4[idx];
    }
    // ---- Stage Wh_seg (32x32 f32 = 1024 floats) into padded smem ----
    {
        const float4* w4 = reinterpret_cast<const float4*>(g_Wh + (size_t)seg0 * F_DIM);
        float4 v = w4[tid];                       // 1024 floats / 4 = 256 float4
        const int e = tid * 4;
        Wh_s[e >> 5][e & 31]           = v.x;     // consecutive elems, same row (32|e pattern)
        Wh_s[(e + 1) >> 5][(e + 1) & 31] = v.y;
        Wh_s[(e + 2) >> 5][(e + 2) & 31] = v.z;
        Wh_s[(e + 3) >> 5][(e + 3) & 31] = v.w;
    }
    __syncthreads();

    // ---- logit_j = dot(f[i, gj, :], Wh[gj, :]) ----
    float logit = 0.f;
    #pragma unroll
    for (int k4 = 0; k4 < F_DIM / 4; k4++) {
        float4 v = fv[k4];
        logit += v.x * Wh_s[lane][k4 * 4 + 0]
               + v.y * Wh_s[lane][k4 * 4 + 1]
               + v.z * Wh_s[lane][k4 * 4 + 2]
               + v.w * Wh_s[lane][k4 * 4 + 3];
    }

    // bad mask: bearing < 0 || distance > 10 || self
    const bool bad = (bearing < 0.f) || (dist > 10.f) || (i == gj);
    const float val = bad ? -1000.f : logit;

    // ---- warp softmax over 32 in-segment entries ----
    float m = val;
    #pragma unroll
    for (int off = 16; off; off >>= 1)
        m = fmaxf(m, __shfl_xor_sync(0xFFFFFFFFu, m, off));
    float e = expf(val - m);
    float ssum = e;
    #pragma unroll
    for (int off = 16; off; off >>= 1)
        ssum += __shfl_xor_sync(0xFFFFFFFFu, ssum, off);
    const float attn = e / ssum;

    // ---- S[i,:] = sum_j attn_j * h_seg[j,:]; lane owns 4 contiguous cols ----
    // LDS.128 per row: lanes hit 32 distinct banks per 8-lane phase (conflict-free).
    float4 acc = make_float4(0.f, 0.f, 0.f, 0.f);
    const float4* hrow4 = reinterpret_cast<const float4*>(&h_seg[0][0]) + lane;
    #pragma unroll
    for (int jj = 0; jj < SEG; jj++) {
        const float a = __shfl_sync(0xFFFFFFFFu, attn, jj);
        float4 hv = hrow4[jj * (H_DIM / 4)];
        acc.x += a * hv.x;
        acc.y += a * hv.y;
        acc.z += a * hv.z;
        acc.w += a * hv.w;
    }

    // seg_size == 32 > 1 always -> no zeroing branch.
    reinterpret_cast<float4*>(S + (size_t)i * H_DIM)[lane] = acc;   // STG.128, coalesced
}

extern "C" void kernel_launch(void* const* d_in, const int* in_sizes, int n_in,
                              void* d_out, int out_size)
{
    // metadata order: f, h, features, hor_bearings_MTX, W_w, W_b, sub_batches
    const float* f        = (const float*)d_in[0];
    const float* h        = (const float*)d_in[1];
    const float* features = (const float*)d_in[2];
    const float* hor      = (const float*)d_in[3];
    const float* W_w      = (const float*)d_in[4];
    const float* W_b      = (const float*)d_in[5];
    float* S = (float*)d_out;

    wh_kernel<<<(T_DIM * F_DIM) / THREADS, THREADS>>>(h, W_w, W_b);
    horizon_attn_kernel<<<T_DIM / ROWS_PER_BLOCK, THREADS>>>(f, h, features, hor, S);
}

// round 3
// speedup vs baseline: 1.9552x; 1.7701x over previous
#include <cuda_runtime.h>
#include <cuda_bf16.h>

#define T_DIM    2048
#define NUM_SEG  64
#define SEG      32
#define F_DIM    32
#define H_DIM    128
#define FEAT_DIM 4

#define ROWS_PER_BLOCK 16      // 2 rows per warp, 8 warps
#define THREADS 256
#define GRID (T_DIM / ROWS_PER_BLOCK)   // 128 blocks -> single wave

#define WT_PITCH 33            // padded pitch for W^T and Wh smem

__global__ __launch_bounds__(THREADS, 1)
void horizon_fused_kernel(const float* __restrict__ f,
                          const float* __restrict__ h,
                          const float* __restrict__ features,
                          const float* __restrict__ hor,
                          const float* __restrict__ W_w,
                          const float* __restrict__ W_b,
                          float* __restrict__ S)
{
    __shared__ float h_seg[SEG][H_DIM];           // 16 KB
    __shared__ float Wt_s[H_DIM][WT_PITCH];       // W^T, padded: 16.9 KB
    __shared__ float Wh_s[SEG][WT_PITCH];         // Wh for this segment: 4.2 KB

    const int tid    = threadIdx.x;
    const int blk    = blockIdx.x;
    const int seg    = blk >> 1;                  // 2 blocks per segment
    const int rowgrp = blk & 1;
    const int seg0   = seg * SEG;

    const int warp = tid >> 5;
    const int lane = tid & 31;

    const int i0 = seg0 + rowgrp * ROWS_PER_BLOCK + warp;      // output row A
    const int i1 = i0 + 8;                                     // output row B
    const int gj = seg0 + lane;                                // segment column

    // ================= Phase 0: issue ALL DRAM loads early =================
    // Their ~600-cycle latency is hidden behind staging + the Wh matmul.
    float4 fv0[F_DIM / 4], fv1[F_DIM / 4];
    {
        const float4* fp0 = reinterpret_cast<const float4*>(f + ((size_t)i0 * T_DIM + gj) * F_DIM);
        const float4* fp1 = reinterpret_cast<const float4*>(f + ((size_t)i1 * T_DIM + gj) * F_DIM);
        #pragma unroll
        for (int k4 = 0; k4 < F_DIM / 4; k4++) { fv0[k4] = fp0[k4]; fv1[k4] = fp1[k4]; }
    }
    const size_t mb0 = (size_t)i0 * T_DIM + gj;
    const size_t mb1 = (size_t)i1 * T_DIM + gj;
    const float bear0 = hor[mb0];
    const float bear1 = hor[mb1];
    const float dist0 = features[mb0 * FEAT_DIM];
    const float dist1 = features[mb1 * FEAT_DIM];

    // ================= Phase 1: stage h_seg + W^T (coalesced) ==============
    {
        const float4* h4  = reinterpret_cast<const float4*>(h + (size_t)seg0 * H_DIM);
        float4*       hs4 = reinterpret_cast<float4*>(&h_seg[0][0]);
        #pragma unroll
        for (int n = tid; n < SEG * H_DIM / 4; n += THREADS)
            hs4[n] = h4[n];

        // W_w is (32 x 128): read coalesced float4, write transposed (padded).
        const float4* w4 = reinterpret_cast<const float4*>(W_w);
        #pragma unroll
        for (int n = tid; n < F_DIM * H_DIM / 4; n += THREADS) {
            const int ff  = n >> 5;          // W row
            const int kg4 = n & 31;          // float4 index along k
            float4 v = w4[n];
            Wt_s[kg4 * 4 + 0][ff] = v.x;
            Wt_s[kg4 * 4 + 1][ff] = v.y;
            Wt_s[kg4 * 4 + 2][ff] = v.z;
            Wt_s[kg4 * 4 + 3][ff] = v.w;
        }
    }
    __syncthreads();

    // ================= Phase 2: Wh for all 32 segment rows =================
    // Warp computes 4 j-rows; lane = output column ff.
    // Wt_s[k][lane]: banks (k+lane)%32 -> conflict-free; h_seg[j][k]: broadcast.
    {
        float acc0 = W_b[lane], acc1 = acc0, acc2 = acc0, acc3 = acc0;
        const int j0 = warp, j1 = warp + 8, j2 = warp + 16, j3 = warp + 24;
        #pragma unroll 16
        for (int k = 0; k < H_DIM; k++) {
            const float w = Wt_s[k][lane];
            acc0 += h_seg[j0][k] * w;
            acc1 += h_seg[j1][k] * w;
            acc2 += h_seg[j2][k] * w;
            acc3 += h_seg[j3][k] * w;
        }
        Wh_s[j0][lane] = acc0;
        Wh_s[j1][lane] = acc1;
        Wh_s[j2][lane] = acc2;
        Wh_s[j3][lane] = acc3;
    }
    __syncthreads();

    // ================= Phase 3: logits (dot f . Wh) ========================
    // Wh_s[lane][ff]: addr lane*33+ff -> banks (lane+ff)%32, conflict-free.
    float logit0 = 0.f, logit1 = 0.f;
    #pragma unroll
    for (int k4 = 0; k4 < F_DIM / 4; k4++) {
        const float w0 = Wh_s[lane][k4 * 4 + 0];
        const float w1 = Wh_s[lane][k4 * 4 + 1];
        const float w2 = Wh_s[lane][k4 * 4 + 2];
        const float w3 = Wh_s[lane][k4 * 4 + 3];
        float4 a = fv0[k4], b = fv1[k4];
        logit0 += a.x * w0 + a.y * w1 + a.z * w2 + a.w * w3;
        logit1 += b.x * w0 + b.y * w1 + b.z * w2 + b.w * w3;
    }

    const bool bad0 = (bear0 < 0.f) || (dist0 > 10.f) || (i0 == gj);
    const bool bad1 = (bear1 < 0.f) || (dist1 > 10.f) || (i1 == gj);
    float v0 = bad0 ? -1000.f : logit0;
    float v1 = bad1 ? -1000.f : logit1;

    // ================= Phase 4: dual warp softmax (interleaved) ============
    float m0 = v0, m1 = v1;
    #pragma unroll
    for (int off = 16; off; off >>= 1) {
        m0 = fmaxf(m0, __shfl_xor_sync(0xFFFFFFFFu, m0, off));
        m1 = fmaxf(m1, __shfl_xor_sync(0xFFFFFFFFu, m1, off));
    }
    float e0 = expf(v0 - m0);
    float e1 = expf(v1 - m1);
    float s0 = e0, s1 = e1;
    #pragma unroll
    for (int off = 16; off; off >>= 1) {
        s0 += __shfl_xor_sync(0xFFFFFFFFu, s0, off);
        s1 += __shfl_xor_sync(0xFFFFFFFFu, s1, off);
    }
    const float attn0 = e0 / s0;
    const float attn1 = e1 / s1;

    // ================= Phase 5: S = attn @ h_seg (shared hv loads) =========
    float4 A0 = make_float4(0.f, 0.f, 0.f, 0.f);
    float4 A1 = make_float4(0.f, 0.f, 0.f, 0.f);
    const float4* hrow4 = reinterpret_cast<const float4*>(&h_seg[0][0]) + lane;
    #pragma unroll
    for (int jj = 0; jj < SEG; jj++) {
        const float a0 = __shfl_sync(0xFFFFFFFFu, attn0, jj);
        const float a1 = __shfl_sync(0xFFFFFFFFu, attn1, jj);
        const float4 hv = hrow4[jj * (H_DIM / 4)];
        A0.x += a0 * hv.x;  A0.y += a0 * hv.y;  A0.z += a0 * hv.z;  A0.w += a0 * hv.w;
        A1.x += a1 * hv.x;  A1.y += a1 * hv.y;  A1.z += a1 * hv.z;  A1.w += a1 * hv.w;
    }

    reinterpret_cast<float4*>(S + (size_t)i0 * H_DIM)[lane] = A0;
    reinterpret_cast<float4*>(S + (size_t)i1 * H_DIM)[lane] = A1;
}

extern "C" void kernel_launch(void* const* d_in, const int* in_sizes, int n_in,
                              void* d_out, int out_size)
{
    // metadata order: f, h, features, hor_bearings_MTX, W_w, W_b, sub_batches
    const float* f        = (const float*)d_in[0];
    const float* h        = (const float*)d_in[1];
    const float* features = (const float*)d_in[2];
    const float* hor      = (const float*)d_in[3];
    const float* W_w      = (const float*)d_in[4];
    const float* W_b      = (const float*)d_in[5];
    float* S = (float*)d_out;

    horizon_fused_kernel<<<GRID, THREADS>>>(f, h, features, hor, W_w, W_b, S);
}